// round 8
// baseline (speedup 1.0000x reference)
#include <cuda_runtime.h>
#include <cuda_fp16.h>
#include <cstdint>

#define NN 100000
#define EE 1600000
#define HH 128

// ---------------- scratch (static device globals; no runtime alloc) ----------------
__device__ int     DEG[NN];
__device__ int     CURSOR[NN];
__device__ int     ROWPTR[NN + 1];
__device__ int     COLIDX[EE];
__device__ float   DINV[NN];
__device__ float   XD[NN];
__device__ float   TSUM[NN];
__device__ __half2 BUF_GH [(size_t)NN * (HH / 2)];  // layer-2 messages
__device__ __half2 BUF_GH2[(size_t)NN * (HH / 2)];  // layer-3 messages
__device__ int     BLKSUM[256];
__device__ int     BLKOFF[256];
__device__ int     SCAN_CTR;

// ---------------- helpers ----------------
__device__ __forceinline__ float tf32r(float x) {
    float r;
    asm("cvt.rna.tf32.f32 %0, %1;" : "=f"(r) : "f"(x));
    return r;
}
__device__ __forceinline__ void mma_tf32(float c[4], uint32_t a0, uint32_t a1,
                                         uint32_t a2, uint32_t a3,
                                         uint32_t b0, uint32_t b1) {
    asm volatile(
        "mma.sync.aligned.m16n8k8.row.col.f32.tf32.tf32.f32 "
        "{%0,%1,%2,%3}, {%4,%5,%6,%7}, {%8,%9}, {%0,%1,%2,%3};"
        : "+f"(c[0]), "+f"(c[1]), "+f"(c[2]), "+f"(c[3])
        : "r"(a0), "r"(a1), "r"(a2), "r"(a3), "r"(b0), "r"(b1));
}
__device__ __forceinline__ void add8(float* a, uint4 u) {
    const __half2* h = reinterpret_cast<const __half2*>(&u);
    #pragma unroll
    for (int j = 0; j < 4; j++) {
        float2 f = __half22float2(h[j]);
        a[2 * j] += f.x; a[2 * j + 1] += f.y;
    }
}

// ---------------- CSR build ----------------
__global__ void k_zero() {
    int i = blockIdx.x * blockDim.x + threadIdx.x;
    if (i < NN) { DEG[i] = 0; CURSOR[i] = 0; }
    if (i == 0) SCAN_CTR = 0;
}
__global__ void k_hist(const int* __restrict__ dst) {
    int e = blockIdx.x * blockDim.x + threadIdx.x;
    if (e < EE) atomicAdd(&DEG[dst[e]], 1);
}
__global__ void k_scan12(const float* __restrict__ x) {
    __shared__ int s[512];
    __shared__ int is_last;
    int i = blockIdx.x * 512 + threadIdx.x;
    int v = (i < NN) ? DEG[i] : 0;
    s[threadIdx.x] = v;
    __syncthreads();
    for (int off = 1; off < 512; off <<= 1) {
        int t = 0;
        if (threadIdx.x >= off) t = s[threadIdx.x - off];
        __syncthreads();
        if (threadIdx.x >= off) s[threadIdx.x] += t;
        __syncthreads();
    }
    if (i < NN) {
        ROWPTR[i] = s[threadIdx.x] - v;
        float di = rsqrtf((float)(v + 1));
        DINV[i] = di;
        XD[i] = x[i] * di;
    }
    if (threadIdx.x == 511) BLKSUM[blockIdx.x] = s[511];
    __threadfence();
    if (threadIdx.x == 0)
        is_last = (atomicAdd(&SCAN_CTR, 1) == gridDim.x - 1);
    __syncthreads();
    if (is_last && threadIdx.x < 256) {
        const int NB = (NN + 511) / 512;
        int bv = (threadIdx.x < NB) ? BLKSUM[threadIdx.x] : 0;
        s[threadIdx.x] = bv;
        __syncthreads();
        for (int off = 1; off < 256; off <<= 1) {
            int t = 0;
            if (threadIdx.x >= off) t = s[threadIdx.x - off];
            __syncthreads();
            if (threadIdx.x >= off) s[threadIdx.x] += t;
            __syncthreads();
        }
        BLKOFF[threadIdx.x] = s[threadIdx.x] - bv;
    }
}
__global__ void k_scan3() {
    int i = blockIdx.x * blockDim.x + threadIdx.x;
    if (i < NN) ROWPTR[i] += BLKOFF[i >> 9];
    if (i == 0) ROWPTR[NN] = EE;
}
__global__ void k_scatter(const int* __restrict__ src, const int* __restrict__ dst) {
    int e = blockIdx.x * blockDim.x + threadIdx.x;
    if (e >= EE) return;
    int d = dst[e];
    int p = ROWPTR[d] + atomicAdd(&CURSOR[d], 1);
    COLIDX[p] = src[e];
}

// ---------------- layer-1 scalar aggregation ----------------
__global__ void k_scalar_agg() {
    int i = blockIdx.x * blockDim.x + threadIdx.x;
    if (i >= NN) return;
    float t = XD[i];
    int e = ROWPTR[i], end = ROWPTR[i + 1];
    for (; e + 4 <= end; e += 4) {
        float a0 = XD[COLIDX[e]],     a1 = XD[COLIDX[e + 1]];
        float a2 = XD[COLIDX[e + 2]], a3 = XD[COLIDX[e + 3]];
        t += (a0 + a1) + (a2 + a3);
    }
    for (; e < end; ++e) t += XD[COLIDX[e]];
    TSUM[i] = t * DINV[i];
}

// ================= fused GEMM kernels (256 threads, 8 warps, CTA = 64 rows) ==========
#define AS_STRIDE 132
#define WT_STRIDE 132
#define SMEM_L23 ((64 * AS_STRIDE + 128 * WT_STRIDE) * 4)
#define SMEM_HEAD ((64 * AS_STRIDE + 64 * WT_STRIDE) * 4)

// load + transpose + round a [128 x NC] K-major W into Wt[n][k], 256 threads
template <int NC>
__device__ __forceinline__ void load_wt(float* Wt, const float* __restrict__ W, int tid) {
    const float4* W4 = reinterpret_cast<const float4*>(W);
    constexpr int ITERS = 128 * (NC / 4) / 256;
    #pragma unroll
    for (int i = 0; i < ITERS; i++) {
        int idx = i * 256 + tid;
        int kr = idx / (NC / 4), q = idx % (NC / 4);
        float4 v = W4[kr * (NC / 4) + q];
        Wt[(q * 4 + 0) * WT_STRIDE + kr] = tf32r(v.x);
        Wt[(q * 4 + 1) * WT_STRIDE + kr] = tf32r(v.y);
        Wt[(q * 4 + 2) * WT_STRIDE + kr] = tf32r(v.z);
        Wt[(q * 4 + 3) * WT_STRIDE + kr] = tf32r(v.w);
    }
}

// CSR gather-aggregate prologue: As[r][:] = tf32(act(dinv*(self+sum nbr)+bias))
template <bool RELU>
__device__ __forceinline__ void agg_prologue(float* As, const __half2* __restrict__ GH,
                                             const float4* __restrict__ bias,
                                             int row0, int tid) {
    int r = tid >> 2, q = tid & 3;
    int node = row0 + r; if (node >= NN) node = NN - 1;
    const uint4* g = reinterpret_cast<const uint4*>(GH);   // 16 uint4 per row
    float acc[32];
    {
        const uint4* p = &g[(size_t)node * 16 + q * 4];
        uint4 u0 = p[0], u1 = p[1], u2 = p[2], u3 = p[3];
        #pragma unroll
        for (int k = 0; k < 32; k++) acc[k] = 0.f;
        add8(acc + 0, u0); add8(acc + 8, u1); add8(acc + 16, u2); add8(acc + 24, u3);
    }
    int e = ROWPTR[node], end = ROWPTR[node + 1];
    for (; e + 2 <= end; e += 2) {
        int s0 = COLIDX[e], s1 = COLIDX[e + 1];
        const uint4* p0 = &g[(size_t)s0 * 16 + q * 4];
        const uint4* p1 = &g[(size_t)s1 * 16 + q * 4];
        uint4 a0 = p0[0], a1 = p0[1], a2 = p0[2], a3 = p0[3];
        uint4 b0 = p1[0], b1 = p1[1], b2 = p1[2], b3 = p1[3];
        add8(acc + 0, a0); add8(acc + 8, a1); add8(acc + 16, a2); add8(acc + 24, a3);
        add8(acc + 0, b0); add8(acc + 8, b1); add8(acc + 16, b2); add8(acc + 24, b3);
    }
    for (; e < end; ++e) {
        const uint4* p = &g[(size_t)COLIDX[e] * 16 + q * 4];
        uint4 u0 = p[0], u1 = p[1], u2 = p[2], u3 = p[3];
        add8(acc + 0, u0); add8(acc + 8, u1); add8(acc + 16, u2); add8(acc + 24, u3);
    }
    float di = DINV[node];
    float* dst = &As[r * AS_STRIDE + q * 32];
    #pragma unroll
    for (int j = 0; j < 8; j++) {
        float4 bb = bias[q * 8 + j];
        float z0 = fmaf(acc[j * 4 + 0], di, bb.x);
        float z1 = fmaf(acc[j * 4 + 1], di, bb.y);
        float z2 = fmaf(acc[j * 4 + 2], di, bb.z);
        float z3 = fmaf(acc[j * 4 + 3], di, bb.w);
        if (RELU) {
            z0 = fmaxf(z0, 0.f); z1 = fmaxf(z1, 0.f);
            z2 = fmaxf(z2, 0.f); z3 = fmaxf(z3, 0.f);
        }
        dst[j * 4 + 0] = tf32r(z0); dst[j * 4 + 1] = tf32r(z1);
        dst[j * 4 + 2] = tf32r(z2); dst[j * 4 + 3] = tf32r(z3);
    }
}

// MMA mainloop, warp tile 16 x (NC/2); epilogue to fp16 messages with DINV scale
template <int NC>
__device__ __forceinline__ void mma_to_msgs(const float* As, const float* Wt,
                                            __half2* __restrict__ GH_out,
                                            int row0, int tid) {
    constexpr int NI = NC / 16;            // 8 for NC=128
    int wid = tid >> 5, lid = tid & 31;
    int g = lid >> 2, tig = lid & 3;
    int wm = wid >> 1, wn = wid & 1;
    const uint32_t* Au = reinterpret_cast<const uint32_t*>(As);
    const uint32_t* Wu = reinterpret_cast<const uint32_t*>(Wt);
    float c[NI][4] = {};
    #pragma unroll
    for (int ks = 0; ks < 16; ks++) {
        int k0 = ks * 8;
        int rb = wm * 16 + g;
        uint32_t a0 = Au[rb * AS_STRIDE + k0 + tig];
        uint32_t a1 = Au[(rb + 8) * AS_STRIDE + k0 + tig];
        uint32_t a2 = Au[rb * AS_STRIDE + k0 + tig + 4];
        uint32_t a3 = Au[(rb + 8) * AS_STRIDE + k0 + tig + 4];
        #pragma unroll
        for (int ni = 0; ni < NI; ni++) {
            int n = wn * (NC / 2) + ni * 8 + g;
            uint32_t b0 = Wu[n * WT_STRIDE + k0 + tig];
            uint32_t b1 = Wu[n * WT_STRIDE + k0 + tig + 4];
            mma_tf32(c[ni], a0, a1, a2, a3, b0, b1);
        }
    }
    int r0 = row0 + wm * 16 + g;
    int r1 = r0 + 8;
    float s0 = (r0 < NN) ? DINV[r0] : 0.f;
    float s1 = (r1 < NN) ? DINV[r1] : 0.f;
    #pragma unroll
    for (int ni = 0; ni < NI; ni++) {
        int c2 = wn * (NC / 4) + ni * 4 + tig;
        if (r0 < NN)
            GH_out[(size_t)r0 * 64 + c2] = __floats2half2_rn(c[ni][0] * s0, c[ni][1] * s0);
        if (r1 < NN)
            GH_out[(size_t)r1 * 64 + c2] = __floats2half2_rn(c[ni][2] * s1, c[ni][3] * s1);
    }
}

// ---- layer 2: expand prologue (rank-1) + GEMM(W2) -> BUF_GH ----
__global__ void __launch_bounds__(256) k_l2(const float* __restrict__ W2,
                                            const float4* __restrict__ W1,
                                            const float4* __restrict__ b1) {
    extern __shared__ __align__(16) float dyn[];
    float* As = dyn;
    float* Wt = dyn + 64 * AS_STRIDE;
    int tid = threadIdx.x;
    int row0 = blockIdx.x * 64;
    // prologue: As[r][c] = tf32(relu(TSUM[r]*W1[c]+b1[c]))
    {
        int r = tid >> 2, q = tid & 3;
        int node = row0 + r; if (node >= NN) node = NN - 1;
        float s = TSUM[node];
        float* dst = &As[r * AS_STRIDE + q * 32];
        #pragma unroll
        for (int j = 0; j < 8; j++) {
            float4 w = W1[q * 8 + j], b = b1[q * 8 + j];
            dst[j * 4 + 0] = tf32r(fmaxf(fmaf(s, w.x, b.x), 0.f));
            dst[j * 4 + 1] = tf32r(fmaxf(fmaf(s, w.y, b.y), 0.f));
            dst[j * 4 + 2] = tf32r(fmaxf(fmaf(s, w.z, b.z), 0.f));
            dst[j * 4 + 3] = tf32r(fmaxf(fmaf(s, w.w, b.w), 0.f));
        }
    }
    load_wt<128>(Wt, W2, tid);
    __syncthreads();
    mma_to_msgs<128>(As, Wt, BUF_GH, row0, tid);
}

// ---- layer 3: agg prologue (relu) + GEMM(W3) -> BUF_GH2 ----
__global__ void __launch_bounds__(256) k_l3(const float* __restrict__ W3,
                                            const float4* __restrict__ b2) {
    extern __shared__ __align__(16) float dyn[];
    float* As = dyn;
    float* Wt = dyn + 64 * AS_STRIDE;
    int tid = threadIdx.x;
    int row0 = blockIdx.x * 64;
    agg_prologue<true>(As, BUF_GH, b2, row0, tid);
    load_wt<128>(Wt, W3, tid);
    __syncthreads();
    mma_to_msgs<128>(As, Wt, BUF_GH2, row0, tid);
}

// ---- head: agg prologue (no relu) + GEMM(Wo) + bo -> out ----
__global__ void __launch_bounds__(256) k_head(const float* __restrict__ Wo,
                                              const float4* __restrict__ b3,
                                              const float* __restrict__ bo,
                                              float* __restrict__ outp) {
    extern __shared__ __align__(16) float dyn[];
    float* As = dyn;
    float* Wt = dyn + 64 * AS_STRIDE;
    int tid = threadIdx.x;
    int row0 = blockIdx.x * 64;
    agg_prologue<false>(As, BUF_GH2, b3, row0, tid);
    load_wt<64>(Wt, Wo, tid);
    __syncthreads();

    int wid = tid >> 5, lid = tid & 31;
    int g = lid >> 2, tig = lid & 3;
    int wm = wid >> 1, wn = wid & 1;
    const uint32_t* Au = reinterpret_cast<const uint32_t*>(As);
    const uint32_t* Wu = reinterpret_cast<const uint32_t*>(Wt);
    float c[4][4] = {};
    #pragma unroll
    for (int ks = 0; ks < 16; ks++) {
        int k0 = ks * 8;
        int rb = wm * 16 + g;
        uint32_t a0 = Au[rb * AS_STRIDE + k0 + tig];
        uint32_t a1 = Au[(rb + 8) * AS_STRIDE + k0 + tig];
        uint32_t a2 = Au[rb * AS_STRIDE + k0 + tig + 4];
        uint32_t a3 = Au[(rb + 8) * AS_STRIDE + k0 + tig + 4];
        #pragma unroll
        for (int ni = 0; ni < 4; ni++) {
            int n = wn * 32 + ni * 8 + g;
            uint32_t b0 = Wu[n * WT_STRIDE + k0 + tig];
            uint32_t b1 = Wu[n * WT_STRIDE + k0 + tig + 4];
            mma_tf32(c[ni], a0, a1, a2, a3, b0, b1);
        }
    }
    int r0 = row0 + wm * 16 + g;
    int r1 = r0 + 8;
    #pragma unroll
    for (int ni = 0; ni < 4; ni++) {
        int col = wn * 32 + ni * 8 + 2 * tig;
        float2 bb = *reinterpret_cast<const float2*>(bo + col);
        if (r0 < NN)
            *reinterpret_cast<float2*>(outp + (size_t)r0 * 64 + col) =
                make_float2(c[ni][0] + bb.x, c[ni][1] + bb.y);
        if (r1 < NN)
            *reinterpret_cast<float2*>(outp + (size_t)r1 * 64 + col) =
                make_float2(c[ni][2] + bb.x, c[ni][3] + bb.y);
    }
}

// ---------------- launch ----------------
extern "C" void kernel_launch(void* const* d_in, const int* in_sizes, int n_in,
                              void* d_out, int out_size) {
    const float* x  = (const float*)d_in[0];
    const int*   ei = (const int*)d_in[1];
    const int*   src = ei;
    const int*   dst = ei + EE;
    const float* W1 = (const float*)d_in[2];
    const float* b1 = (const float*)d_in[3];
    const float* W2 = (const float*)d_in[4];
    const float* b2 = (const float*)d_in[5];
    const float* W3 = (const float*)d_in[6];
    const float* b3 = (const float*)d_in[7];
    const float* Wo = (const float*)d_in[8];
    const float* bo = (const float*)d_in[9];
    float* out = (float*)d_out;

    cudaFuncSetAttribute(k_l2,   cudaFuncAttributeMaxDynamicSharedMemorySize, SMEM_L23);
    cudaFuncSetAttribute(k_l3,   cudaFuncAttributeMaxDynamicSharedMemorySize, SMEM_L23);
    cudaFuncSetAttribute(k_head, cudaFuncAttributeMaxDynamicSharedMemorySize, SMEM_HEAD);

    const int NG = (NN + 63) / 64;   // 1563

    // CSR build
    k_zero   <<<(NN + 255) / 256, 256>>>();
    k_hist   <<<(EE + 255) / 256, 256>>>(dst);
    k_scan12 <<<(NN + 511) / 512, 512>>>(x);
    k_scan3  <<<(NN + 255) / 256, 256>>>();
    k_scatter<<<(EE + 255) / 256, 256>>>(src, dst);

    // layer 1 scalar aggregate
    k_scalar_agg<<<(NN + 255) / 256, 256>>>();

    // fused layers
    k_l2  <<<NG, 256, SMEM_L23 >>>(W2, (const float4*)W1, (const float4*)b1);
    k_l3  <<<NG, 256, SMEM_L23 >>>(W3, (const float4*)b2);
    k_head<<<NG, 256, SMEM_HEAD>>>(Wo, (const float4*)b3, bo, out);
}

// round 9
// speedup vs baseline: 1.2293x; 1.2293x over previous
#include <cuda_runtime.h>
#include <cuda_fp16.h>
#include <cstdint>

#define NN 100000
#define EE 1600000
#define HH 128

// ---------------- scratch (static device globals; no runtime alloc) ----------------
__device__ int     DEG[NN];
__device__ int     CURSOR[NN];
__device__ int     ROWPTR[NN + 1];
__device__ int     COLIDX[EE];
__device__ float   DINV[NN];
__device__ float   XD[NN];
__device__ float   TSUM[NN];
__device__ __half2 BUF_GH[(size_t)NN * (HH / 2)];   // fp16 messages g = h * dinv
__device__ __half2 BUF_ZH[(size_t)NN * (HH / 2)];   // fp16 activations z
__device__ int     BLKSUM[256];
__device__ int     BLKOFF[256];
__device__ int     SCAN_CTR;

// ---------------- helpers ----------------
__device__ __forceinline__ float tf32r(float x) {
    float r;
    asm("cvt.rna.tf32.f32 %0, %1;" : "=f"(r) : "f"(x));
    return r;
}
__device__ __forceinline__ void mma_tf32(float c[4], uint32_t a0, uint32_t a1,
                                         uint32_t a2, uint32_t a3,
                                         uint32_t b0, uint32_t b1) {
    asm volatile(
        "mma.sync.aligned.m16n8k8.row.col.f32.tf32.tf32.f32 "
        "{%0,%1,%2,%3}, {%4,%5,%6,%7}, {%8,%9}, {%0,%1,%2,%3};"
        : "+f"(c[0]), "+f"(c[1]), "+f"(c[2]), "+f"(c[3])
        : "r"(a0), "r"(a1), "r"(a2), "r"(a3), "r"(b0), "r"(b1));
}

// ---------------- CSR build ----------------
__global__ void k_zero() {
    int i = blockIdx.x * blockDim.x + threadIdx.x;
    if (i < NN) { DEG[i] = 0; CURSOR[i] = 0; }
    if (i == 0) SCAN_CTR = 0;
}
__global__ void k_hist(const int* __restrict__ dst) {
    int e = blockIdx.x * blockDim.x + threadIdx.x;
    if (e < EE) atomicAdd(&DEG[dst[e]], 1);
}
__global__ void k_scan12(const float* __restrict__ x) {
    __shared__ int s[512];
    __shared__ int is_last;
    int i = blockIdx.x * 512 + threadIdx.x;
    int v = (i < NN) ? DEG[i] : 0;
    s[threadIdx.x] = v;
    __syncthreads();
    for (int off = 1; off < 512; off <<= 1) {
        int t = 0;
        if (threadIdx.x >= off) t = s[threadIdx.x - off];
        __syncthreads();
        if (threadIdx.x >= off) s[threadIdx.x] += t;
        __syncthreads();
    }
    if (i < NN) {
        ROWPTR[i] = s[threadIdx.x] - v;
        float di = rsqrtf((float)(v + 1));
        DINV[i] = di;
        XD[i] = x[i] * di;
    }
    if (threadIdx.x == 511) BLKSUM[blockIdx.x] = s[511];
    __threadfence();
    if (threadIdx.x == 0)
        is_last = (atomicAdd(&SCAN_CTR, 1) == gridDim.x - 1);
    __syncthreads();
    if (is_last && threadIdx.x < 256) {
        const int NB = (NN + 511) / 512;
        int bv = (threadIdx.x < NB) ? BLKSUM[threadIdx.x] : 0;
        s[threadIdx.x] = bv;
        __syncthreads();
        for (int off = 1; off < 256; off <<= 1) {
            int t = 0;
            if (threadIdx.x >= off) t = s[threadIdx.x - off];
            __syncthreads();
            if (threadIdx.x >= off) s[threadIdx.x] += t;
            __syncthreads();
        }
        BLKOFF[threadIdx.x] = s[threadIdx.x] - bv;
    }
}
__global__ void k_scan3() {
    int i = blockIdx.x * blockDim.x + threadIdx.x;
    if (i < NN) ROWPTR[i] += BLKOFF[i >> 9];
    if (i == 0) ROWPTR[NN] = EE;
}
__global__ void k_scatter(const int* __restrict__ src, const int* __restrict__ dst) {
    int e = blockIdx.x * blockDim.x + threadIdx.x;
    if (e >= EE) return;
    int d = dst[e];
    int p = ROWPTR[d] + atomicAdd(&CURSOR[d], 1);
    COLIDX[p] = src[e];
}

// ---------------- layer-1 scalar aggregation ----------------
__global__ void k_scalar_agg() {
    int i = blockIdx.x * blockDim.x + threadIdx.x;
    if (i >= NN) return;
    float t = XD[i];
    int e = ROWPTR[i], end = ROWPTR[i + 1];
    for (; e + 4 <= end; e += 4) {
        float a0 = XD[COLIDX[e]],     a1 = XD[COLIDX[e + 1]];
        float a2 = XD[COLIDX[e + 2]], a3 = XD[COLIDX[e + 3]];
        t += (a0 + a1) + (a2 + a3);
    }
    for (; e < end; ++e) t += XD[COLIDX[e]];
    TSUM[i] = t * DINV[i];
}

// ---------------- aggregation (fp16 messages in, fp32 accumulate, fp16 out) ----------
__device__ __forceinline__ void acc_gh(float4& acc, uint2 u) {
    float2 f0 = __half22float2(*reinterpret_cast<__half2*>(&u.x));
    float2 f1 = __half22float2(*reinterpret_cast<__half2*>(&u.y));
    acc.x += f0.x; acc.y += f0.y; acc.z += f1.x; acc.w += f1.y;
}

template <bool RELU>
__global__ void k_agg(const float4* __restrict__ bias) {
    int node = (blockIdx.x * blockDim.x + threadIdx.x) >> 5;
    if (node >= NN) return;
    int lane = threadIdx.x & 31;
    const uint2* g = reinterpret_cast<const uint2*>(BUF_GH);
    float4 acc = make_float4(0.f, 0.f, 0.f, 0.f);
    acc_gh(acc, g[node * 32 + lane]);                 // self-loop term
    int e = ROWPTR[node], end = ROWPTR[node + 1];
    for (; e + 4 <= end; e += 4) {
        int s0 = COLIDX[e], s1 = COLIDX[e + 1], s2 = COLIDX[e + 2], s3 = COLIDX[e + 3];
        uint2 u0 = g[s0 * 32 + lane], u1 = g[s1 * 32 + lane];
        uint2 u2 = g[s2 * 32 + lane], u3 = g[s3 * 32 + lane];
        acc_gh(acc, u0); acc_gh(acc, u1); acc_gh(acc, u2); acc_gh(acc, u3);
    }
    for (; e < end; ++e) acc_gh(acc, g[COLIDX[e] * 32 + lane]);
    float di = DINV[node];
    float4 b = bias[lane];
    float4 r = make_float4(fmaf(acc.x, di, b.x), fmaf(acc.y, di, b.y),
                           fmaf(acc.z, di, b.z), fmaf(acc.w, di, b.w));
    if (RELU) {
        r.x = fmaxf(r.x, 0.f); r.y = fmaxf(r.y, 0.f);
        r.z = fmaxf(r.z, 0.f); r.w = fmaxf(r.w, 0.f);
    }
    // fp16-RN has the same 10-bit mantissa as tf32 -> replaces tf32 rounding exactly
    __half2 h0 = __floats2half2_rn(r.x, r.y);
    __half2 h1 = __floats2half2_rn(r.z, r.w);
    uint2 o;
    o.x = *reinterpret_cast<uint32_t*>(&h0);
    o.y = *reinterpret_cast<uint32_t*>(&h1);
    reinterpret_cast<uint2*>(BUF_ZH)[node * 32 + lane] = o;
}

// ================= GEMM building blocks ==========
#define AS_STRIDE 132
#define WT_STRIDE 132
#define SMEM_GTC ((64 * AS_STRIDE + 128 * WT_STRIDE) * 4)
#define SMEM_GTO ((64 * AS_STRIDE + 64 * WT_STRIDE) * 4)

// A-tile load from fp16 activations (exact half->float), NT threads
template <int NT>
__device__ __forceinline__ void load_a_fp16(float* As, int row0, int tid) {
    const uint4* Z4 = reinterpret_cast<const uint4*>(BUF_ZH);  // 16 uint4 per row
    #pragma unroll
    for (int i = 0; i < 1024 / NT; i++) {
        int idx = i * NT + tid;
        int rr = idx >> 4, q = idx & 15;
        int grow = row0 + rr; if (grow >= NN) grow = NN - 1;
        uint4 u = Z4[(size_t)grow * 16 + q];
        const __half2* h = reinterpret_cast<const __half2*>(&u);
        float* p = &As[rr * AS_STRIDE + q * 8];
        #pragma unroll
        for (int j = 0; j < 4; j++) {
            float2 f = __half22float2(h[j]);
            p[2 * j] = f.x; p[2 * j + 1] = f.y;
        }
    }
}

// load + transpose + round a [128 x NC] K-major W into Wt[n][k], NT threads
template <int NC, int NT>
__device__ __forceinline__ void load_wt(float* Wt, const float* __restrict__ W, int tid) {
    const float4* W4 = reinterpret_cast<const float4*>(W);
    constexpr int ITERS = 128 * (NC / 4) / NT;
    #pragma unroll
    for (int i = 0; i < ITERS; i++) {
        int idx = i * NT + tid;
        int kr = idx / (NC / 4), q = idx % (NC / 4);
        float4 v = W4[kr * (NC / 4) + q];
        Wt[(q * 4 + 0) * WT_STRIDE + kr] = tf32r(v.x);
        Wt[(q * 4 + 1) * WT_STRIDE + kr] = tf32r(v.y);
        Wt[(q * 4 + 2) * WT_STRIDE + kr] = tf32r(v.z);
        Wt[(q * 4 + 3) * WT_STRIDE + kr] = tf32r(v.w);
    }
}

// ---- layer 2: expand prologue (rank-1) fused into GEMM(W2) -> BUF_GH, 256 threads ----
__global__ void __launch_bounds__(256) k_l2(const float* __restrict__ W2,
                                            const float4* __restrict__ W1,
                                            const float4* __restrict__ b1) {
    extern __shared__ __align__(16) float dyn[];
    float* As = dyn;
    float* Wt = dyn + 64 * AS_STRIDE;
    int tid = threadIdx.x;
    int row0 = blockIdx.x * 64;
    // prologue: As[r][c] = tf32(relu(TSUM[r]*W1[c]+b1[c]))
    {
        int r = tid >> 2, q = tid & 3;
        int node = row0 + r; if (node >= NN) node = NN - 1;
        float s = TSUM[node];
        float* dst = &As[r * AS_STRIDE + q * 32];
        #pragma unroll
        for (int j = 0; j < 8; j++) {
            float4 w = W1[q * 8 + j], b = b1[q * 8 + j];
            dst[j * 4 + 0] = tf32r(fmaxf(fmaf(s, w.x, b.x), 0.f));
            dst[j * 4 + 1] = tf32r(fmaxf(fmaf(s, w.y, b.y), 0.f));
            dst[j * 4 + 2] = tf32r(fmaxf(fmaf(s, w.z, b.z), 0.f));
            dst[j * 4 + 3] = tf32r(fmaxf(fmaf(s, w.w, b.w), 0.f));
        }
    }
    load_wt<128, 256>(Wt, W2, tid);
    __syncthreads();

    // 8 warps, warp tile 16x64
    int wid = tid >> 5, lid = tid & 31;
    int g = lid >> 2, tig = lid & 3;
    int wm = wid >> 1, wn = wid & 1;
    const uint32_t* Au = reinterpret_cast<const uint32_t*>(As);
    const uint32_t* Wu = reinterpret_cast<const uint32_t*>(Wt);
    float c[8][4] = {};
    #pragma unroll
    for (int ks = 0; ks < 16; ks++) {
        int k0 = ks * 8;
        int rb = wm * 16 + g;
        uint32_t a0 = Au[rb * AS_STRIDE + k0 + tig];
        uint32_t a1 = Au[(rb + 8) * AS_STRIDE + k0 + tig];
        uint32_t a2 = Au[rb * AS_STRIDE + k0 + tig + 4];
        uint32_t a3 = Au[(rb + 8) * AS_STRIDE + k0 + tig + 4];
        #pragma unroll
        for (int ni = 0; ni < 8; ni++) {
            int n = wn * 64 + ni * 8 + g;
            uint32_t b0 = Wu[n * WT_STRIDE + k0 + tig];
            uint32_t b1 = Wu[n * WT_STRIDE + k0 + tig + 4];
            mma_tf32(c[ni], a0, a1, a2, a3, b0, b1);
        }
    }
    int r0 = row0 + wm * 16 + g;
    int r1 = r0 + 8;
    float s0 = (r0 < NN) ? DINV[r0] : 0.f;
    float s1 = (r1 < NN) ? DINV[r1] : 0.f;
    #pragma unroll
    for (int ni = 0; ni < 8; ni++) {
        int c2 = wn * 32 + ni * 4 + tig;
        if (r0 < NN)
            BUF_GH[(size_t)r0 * 64 + c2] = __floats2half2_rn(c[ni][0] * s0, c[ni][1] * s0);
        if (r1 < NN)
            BUF_GH[(size_t)r1 * 64 + c2] = __floats2half2_rn(c[ni][2] * s1, c[ni][3] * s1);
    }
}

// ---- tf32 GEMM (layer 3): BUF_GH = fp16(DINV * (BUF_ZH @ W)), 128 threads ----
__global__ void __launch_bounds__(128) k_gemm_tc(const float* __restrict__ W) {
    extern __shared__ __align__(16) float dyn[];
    float* As = dyn;                       // [64][132]
    float* Wt = dyn + 64 * AS_STRIDE;      // [128][132]
    int tid = threadIdx.x, wid = tid >> 5, lid = tid & 31;
    int g = lid >> 2, tig = lid & 3;
    int wm = wid >> 1, wn = wid & 1;
    int row0 = blockIdx.x * 64;

    load_a_fp16<128>(As, row0, tid);
    load_wt<128, 128>(Wt, W, tid);
    __syncthreads();

    const uint32_t* Au = reinterpret_cast<const uint32_t*>(As);
    const uint32_t* Wu = reinterpret_cast<const uint32_t*>(Wt);
    float c[2][8][4] = {};

    #pragma unroll
    for (int ks = 0; ks < 16; ks++) {
        int k0 = ks * 8;
        uint32_t a[2][4];
        #pragma unroll
        for (int mi = 0; mi < 2; mi++) {
            int rb = wm * 32 + mi * 16 + g;
            a[mi][0] = Au[rb * AS_STRIDE + k0 + tig];
            a[mi][1] = Au[(rb + 8) * AS_STRIDE + k0 + tig];
            a[mi][2] = Au[rb * AS_STRIDE + k0 + tig + 4];
            a[mi][3] = Au[(rb + 8) * AS_STRIDE + k0 + tig + 4];
        }
        uint32_t b[8][2];
        #pragma unroll
        for (int ni = 0; ni < 8; ni++) {
            int n = wn * 64 + ni * 8 + g;
            b[ni][0] = Wu[n * WT_STRIDE + k0 + tig];
            b[ni][1] = Wu[n * WT_STRIDE + k0 + tig + 4];
        }
        #pragma unroll
        for (int mi = 0; mi < 2; mi++)
            #pragma unroll
            for (int ni = 0; ni < 8; ni++)
                mma_tf32(c[mi][ni], a[mi][0], a[mi][1], a[mi][2], a[mi][3],
                         b[ni][0], b[ni][1]);
    }

    #pragma unroll
    for (int mi = 0; mi < 2; mi++) {
        int r0 = row0 + wm * 32 + mi * 16 + g;
        int r1 = r0 + 8;
        float s0 = (r0 < NN) ? DINV[r0] : 0.f;
        float s1 = (r1 < NN) ? DINV[r1] : 0.f;
        #pragma unroll
        for (int ni = 0; ni < 8; ni++) {
            int c2 = wn * 32 + ni * 4 + tig;
            if (r0 < NN)
                BUF_GH[(size_t)r0 * 64 + c2] =
                    __floats2half2_rn(c[mi][ni][0] * s0, c[mi][ni][1] * s0);
            if (r1 < NN)
                BUF_GH[(size_t)r1 * 64 + c2] =
                    __floats2half2_rn(c[mi][ni][2] * s1, c[mi][ni][3] * s1);
        }
    }
}

// ---- head GEMM: out = (BUF_ZH @ Wo) + bo, 128 threads ----
__global__ void __launch_bounds__(128) k_gemm_tc_out(const float* __restrict__ W,
                                                     const float* __restrict__ bias,
                                                     float* __restrict__ outp) {
    extern __shared__ __align__(16) float dyn[];
    float* As = dyn;                       // [64][132]
    float* Wt = dyn + 64 * AS_STRIDE;      // [64][132]
    int tid = threadIdx.x, wid = tid >> 5, lid = tid & 31;
    int g = lid >> 2, tig = lid & 3;
    int wm = wid >> 1, wn = wid & 1;
    int row0 = blockIdx.x * 64;

    load_a_fp16<128>(As, row0, tid);
    load_wt<64, 128>(Wt, W, tid);
    __syncthreads();

    const uint32_t* Au = reinterpret_cast<const uint32_t*>(As);
    const uint32_t* Wu = reinterpret_cast<const uint32_t*>(Wt);
    float c[2][4][4] = {};

    #pragma unroll
    for (int ks = 0; ks < 16; ks++) {
        int k0 = ks * 8;
        uint32_t a[2][4];
        #pragma unroll
        for (int mi = 0; mi < 2; mi++) {
            int rb = wm * 32 + mi * 16 + g;
            a[mi][0] = Au[rb * AS_STRIDE + k0 + tig];
            a[mi][1] = Au[(rb + 8) * AS_STRIDE + k0 + tig];
            a[mi][2] = Au[rb * AS_STRIDE + k0 + tig + 4];
            a[mi][3] = Au[(rb + 8) * AS_STRIDE + k0 + tig + 4];
        }
        uint32_t b[4][2];
        #pragma unroll
        for (int ni = 0; ni < 4; ni++) {
            int n = wn * 32 + ni * 8 + g;
            b[ni][0] = Wu[n * WT_STRIDE + k0 + tig];
            b[ni][1] = Wu[n * WT_STRIDE + k0 + tig + 4];
        }
        #pragma unroll
        for (int mi = 0; mi < 2; mi++)
            #pragma unroll
            for (int ni = 0; ni < 4; ni++)
                mma_tf32(c[mi][ni], a[mi][0], a[mi][1], a[mi][2], a[mi][3],
                         b[ni][0], b[ni][1]);
    }

    #pragma unroll
    for (int mi = 0; mi < 2; mi++) {
        int r0 = row0 + wm * 32 + mi * 16 + g;
        int r1 = r0 + 8;
        #pragma unroll
        for (int ni = 0; ni < 4; ni++) {
            int col = wn * 32 + ni * 8 + 2 * tig;
            float2 bb = *reinterpret_cast<const float2*>(bias + col);
            if (r0 < NN)
                *reinterpret_cast<float2*>(outp + (size_t)r0 * 64 + col) =
                    make_float2(c[mi][ni][0] + bb.x, c[mi][ni][1] + bb.y);
            if (r1 < NN)
                *reinterpret_cast<float2*>(outp + (size_t)r1 * 64 + col) =
                    make_float2(c[mi][ni][2] + bb.x, c[mi][ni][3] + bb.y);
        }
    }
}

// ---------------- launch ----------------
extern "C" void kernel_launch(void* const* d_in, const int* in_sizes, int n_in,
                              void* d_out, int out_size) {
    const float* x  = (const float*)d_in[0];
    const int*   ei = (const int*)d_in[1];
    const int*   src = ei;
    const int*   dst = ei + EE;
    const float* W1 = (const float*)d_in[2];
    const float* b1 = (const float*)d_in[3];
    const float* W2 = (const float*)d_in[4];
    const float* b2 = (const float*)d_in[5];
    const float* W3 = (const float*)d_in[6];
    const float* b3 = (const float*)d_in[7];
    const float* Wo = (const float*)d_in[8];
    const float* bo = (const float*)d_in[9];
    float* out = (float*)d_out;

    cudaFuncSetAttribute(k_l2,         cudaFuncAttributeMaxDynamicSharedMemorySize, SMEM_GTC);
    cudaFuncSetAttribute(k_gemm_tc,    cudaFuncAttributeMaxDynamicSharedMemorySize, SMEM_GTC);
    cudaFuncSetAttribute(k_gemm_tc_out,cudaFuncAttributeMaxDynamicSharedMemorySize, SMEM_GTO);

    const int NG = (NN + 63) / 64;   // 1563

    // CSR build
    k_zero   <<<(NN + 255) / 256, 256>>>();
    k_hist   <<<(EE + 255) / 256, 256>>>(dst);
    k_scan12 <<<(NN + 511) / 512, 512>>>(x);
    k_scan3  <<<(NN + 255) / 256, 256>>>();
    k_scatter<<<(EE + 255) / 256, 256>>>(src, dst);

    // layer 1 scalar aggregate + fused expand/GEMM(W2) -> messages
    k_scalar_agg<<<(NN + 255) / 256, 256>>>();
    k_l2<<<NG, 256, SMEM_GTC>>>(W2, (const float4*)W1, (const float4*)b1);

    // layer 2 agg -> fp16 activations; layer 3 GEMM -> messages
    k_agg<true><<<(NN + 7) / 8, 256>>>((const float4*)b2);
    k_gemm_tc<<<NG, 128, SMEM_GTC>>>(W3);

    // layer 3 agg -> fp16 activations; head GEMM -> out
    k_agg<false><<<(NN + 7) / 8, 256>>>((const float4*)b3);
    k_gemm_tc_out<<<NG, 128, SMEM_GTO>>>(Wo, bo, out);
}

// round 10
// speedup vs baseline: 1.5690x; 1.2763x over previous
#include <cuda_runtime.h>
#include <cuda_fp16.h>
#include <cstdint>

#define NN 100000
#define EE 1600000
#define HH 128

// ---------------- scratch (static device globals; no runtime alloc) ----------------
__device__ int     DEG[NN];
__device__ int     CURSOR[NN];
__device__ int     ROWPTR[NN + 1];
__device__ int     COLIDX[EE];
__device__ float   DINV[NN];
__device__ float   XD[NN];
__device__ float   TSUM[NN];
__device__ __half2 BUF_GH[(size_t)NN * (HH / 2)];   // fp16 messages g = h * dinv
__device__ __half2 BUF_ZH[(size_t)NN * (HH / 2)];   // fp16 activations z
__device__ int     BLKSUM[256];
__device__ int     BLKOFF[256];
__device__ int     SCAN_CTR;

// ---------------- helpers ----------------
__device__ __forceinline__ void mma_f16(float c[4], uint32_t a0, uint32_t a1,
                                        uint32_t a2, uint32_t a3,
                                        uint32_t b0, uint32_t b1) {
    asm volatile(
        "mma.sync.aligned.m16n8k16.row.col.f32.f16.f16.f32 "
        "{%0,%1,%2,%3}, {%4,%5,%6,%7}, {%8,%9}, {%0,%1,%2,%3};"
        : "+f"(c[0]), "+f"(c[1]), "+f"(c[2]), "+f"(c[3])
        : "r"(a0), "r"(a1), "r"(a2), "r"(a3), "r"(b0), "r"(b1));
}

// ---------------- CSR build ----------------
__global__ void k_zero() {
    int i = blockIdx.x * blockDim.x + threadIdx.x;
    if (i < NN) { DEG[i] = 0; CURSOR[i] = 0; }
    if (i == 0) SCAN_CTR = 0;
}
__global__ void k_hist(const int* __restrict__ dst) {
    int e = blockIdx.x * blockDim.x + threadIdx.x;
    if (e < EE) atomicAdd(&DEG[dst[e]], 1);
}
__global__ void k_scan12(const float* __restrict__ x) {
    __shared__ int s[512];
    __shared__ int is_last;
    int i = blockIdx.x * 512 + threadIdx.x;
    int v = (i < NN) ? DEG[i] : 0;
    s[threadIdx.x] = v;
    __syncthreads();
    for (int off = 1; off < 512; off <<= 1) {
        int t = 0;
        if (threadIdx.x >= off) t = s[threadIdx.x - off];
        __syncthreads();
        if (threadIdx.x >= off) s[threadIdx.x] += t;
        __syncthreads();
    }
    if (i < NN) {
        ROWPTR[i] = s[threadIdx.x] - v;
        float di = rsqrtf((float)(v + 1));
        DINV[i] = di;
        XD[i] = x[i] * di;
    }
    if (threadIdx.x == 511) BLKSUM[blockIdx.x] = s[511];
    __threadfence();
    if (threadIdx.x == 0)
        is_last = (atomicAdd(&SCAN_CTR, 1) == gridDim.x - 1);
    __syncthreads();
    if (is_last && threadIdx.x < 256) {
        const int NB = (NN + 511) / 512;
        int bv = (threadIdx.x < NB) ? BLKSUM[threadIdx.x] : 0;
        s[threadIdx.x] = bv;
        __syncthreads();
        for (int off = 1; off < 256; off <<= 1) {
            int t = 0;
            if (threadIdx.x >= off) t = s[threadIdx.x - off];
            __syncthreads();
            if (threadIdx.x >= off) s[threadIdx.x] += t;
            __syncthreads();
        }
        BLKOFF[threadIdx.x] = s[threadIdx.x] - bv;
    }
}
__global__ void k_scan3() {
    int i = blockIdx.x * blockDim.x + threadIdx.x;
    if (i < NN) ROWPTR[i] += BLKOFF[i >> 9];
    if (i == 0) ROWPTR[NN] = EE;
}
__global__ void k_scatter(const int* __restrict__ src, const int* __restrict__ dst) {
    int e = blockIdx.x * blockDim.x + threadIdx.x;
    if (e >= EE) return;
    int d = dst[e];
    int p = ROWPTR[d] + atomicAdd(&CURSOR[d], 1);
    COLIDX[p] = src[e];
}

// ---------------- layer-1 scalar aggregation ----------------
__global__ void k_scalar_agg() {
    int i = blockIdx.x * blockDim.x + threadIdx.x;
    if (i >= NN) return;
    float t = XD[i];
    int e = ROWPTR[i], end = ROWPTR[i + 1];
    for (; e + 4 <= end; e += 4) {
        float a0 = XD[COLIDX[e]],     a1 = XD[COLIDX[e + 1]];
        float a2 = XD[COLIDX[e + 2]], a3 = XD[COLIDX[e + 3]];
        t += (a0 + a1) + (a2 + a3);
    }
    for (; e < end; ++e) t += XD[COLIDX[e]];
    TSUM[i] = t * DINV[i];
}

// ---------------- aggregation (fp16 messages in, fp32 accumulate, fp16 out) ----------
__device__ __forceinline__ void acc_gh(float4& acc, uint2 u) {
    float2 f0 = __half22float2(*reinterpret_cast<__half2*>(&u.x));
    float2 f1 = __half22float2(*reinterpret_cast<__half2*>(&u.y));
    acc.x += f0.x; acc.y += f0.y; acc.z += f1.x; acc.w += f1.y;
}

template <bool RELU>
__global__ void k_agg(const float4* __restrict__ bias) {
    int node = (blockIdx.x * blockDim.x + threadIdx.x) >> 5;
    if (node >= NN) return;
    int lane = threadIdx.x & 31;
    const uint2* g = reinterpret_cast<const uint2*>(BUF_GH);
    float4 acc = make_float4(0.f, 0.f, 0.f, 0.f);
    acc_gh(acc, g[node * 32 + lane]);                 // self-loop term
    int e = ROWPTR[node], end = ROWPTR[node + 1];
    for (; e + 4 <= end; e += 4) {
        int s0 = COLIDX[e], s1 = COLIDX[e + 1], s2 = COLIDX[e + 2], s3 = COLIDX[e + 3];
        uint2 u0 = g[s0 * 32 + lane], u1 = g[s1 * 32 + lane];
        uint2 u2 = g[s2 * 32 + lane], u3 = g[s3 * 32 + lane];
        acc_gh(acc, u0); acc_gh(acc, u1); acc_gh(acc, u2); acc_gh(acc, u3);
    }
    for (; e < end; ++e) acc_gh(acc, g[COLIDX[e] * 32 + lane]);
    float di = DINV[node];
    float4 b = bias[lane];
    float4 r = make_float4(fmaf(acc.x, di, b.x), fmaf(acc.y, di, b.y),
                           fmaf(acc.z, di, b.z), fmaf(acc.w, di, b.w));
    if (RELU) {
        r.x = fmaxf(r.x, 0.f); r.y = fmaxf(r.y, 0.f);
        r.z = fmaxf(r.z, 0.f); r.w = fmaxf(r.w, 0.f);
    }
    __half2 h0 = __floats2half2_rn(r.x, r.y);
    __half2 h1 = __floats2half2_rn(r.z, r.w);
    uint2 o;
    o.x = *reinterpret_cast<uint32_t*>(&h0);
    o.y = *reinterpret_cast<uint32_t*>(&h1);
    reinterpret_cast<uint2*>(BUF_ZH)[node * 32 + lane] = o;
}

// ================= fp16 HMMA GEMMs (BM=128, 512 threads, 16 warps) ==================
// A in smem as halves [128][ASH], W transposed Wt[n][k] halves [NC][ASH].
// Fragment loads: bank = (4g + tig + const) mod 32 -> conflict-free (ASH/2 = 68 words).
#define ASH 136
#define SMEM_G128 ((128 * ASH + 128 * ASH) * 2)
#define SMEM_G64  ((128 * ASH + 64 * ASH) * 2)

// copy fp16 activations (BM=128 rows x 128 halves) into As
__device__ __forceinline__ void load_a_h(__half* As, int row0, int tid) {
    const uint4* Z4 = reinterpret_cast<const uint4*>(BUF_ZH);  // 16 uint4 per row
    #pragma unroll
    for (int i = 0; i < 4; i++) {                               // 2048 / 512
        int idx = i * 512 + tid;
        int rr = idx >> 4, q = idx & 15;
        int grow = row0 + rr; if (grow >= NN) grow = NN - 1;
        uint4 u = Z4[(size_t)grow * 16 + q];
        *reinterpret_cast<uint4*>(reinterpret_cast<char*>(As) + rr * (ASH * 2) + q * 16) = u;
    }
}

// load [128 x NC] K-major fp32 W, convert fp16, store transposed Wt[n][k]
template <int NC>
__device__ __forceinline__ void load_wt_h(__half* Wt, const float* __restrict__ W, int tid) {
    const float4* W4 = reinterpret_cast<const float4*>(W);
    constexpr int ITERS = 128 * (NC / 4) / 512;
    #pragma unroll
    for (int i = 0; i < ITERS; i++) {
        int idx = i * 512 + tid;
        int kr = idx / (NC / 4), q = idx % (NC / 4);
        float4 v = W4[kr * (NC / 4) + q];
        Wt[(q * 4 + 0) * ASH + kr] = __float2half_rn(v.x);
        Wt[(q * 4 + 1) * ASH + kr] = __float2half_rn(v.y);
        Wt[(q * 4 + 2) * ASH + kr] = __float2half_rn(v.z);
        Wt[(q * 4 + 3) * ASH + kr] = __float2half_rn(v.w);
    }
}

// HMMA mainloop, warp tile 16 x (8*NI); accumulators fp32
template <int NI>
__device__ __forceinline__ void hmma_loop(float c[NI][4], const __half* As,
                                          const __half* Wt, int wm, int wn,
                                          int g, int tig) {
    const char* Ab = reinterpret_cast<const char*>(As);
    const char* Wb = reinterpret_cast<const char*>(Wt);
    #pragma unroll
    for (int ks = 0; ks < 8; ks++) {
        int k0 = ks * 16;
        int rb = wm * 16 + g;
        uint32_t a0 = *reinterpret_cast<const uint32_t*>(Ab + (rb * ASH + k0 + 2 * tig) * 2);
        uint32_t a1 = *reinterpret_cast<const uint32_t*>(Ab + ((rb + 8) * ASH + k0 + 2 * tig) * 2);
        uint32_t a2 = *reinterpret_cast<const uint32_t*>(Ab + (rb * ASH + k0 + 8 + 2 * tig) * 2);
        uint32_t a3 = *reinterpret_cast<const uint32_t*>(Ab + ((rb + 8) * ASH + k0 + 8 + 2 * tig) * 2);
        #pragma unroll
        for (int ni = 0; ni < NI; ni++) {
            int n = wn * (8 * NI) + ni * 8 + g;
            uint32_t b0 = *reinterpret_cast<const uint32_t*>(Wb + (n * ASH + k0 + 2 * tig) * 2);
            uint32_t b1 = *reinterpret_cast<const uint32_t*>(Wb + (n * ASH + k0 + 8 + 2 * tig) * 2);
            mma_f16(c[ni], a0, a1, a2, a3, b0, b1);
        }
    }
}

// ---- layer 2: expand prologue (rank-1) fused into GEMM(W2) -> BUF_GH ----
__global__ void __launch_bounds__(512) k_l2(const float* __restrict__ W2,
                                            const float4* __restrict__ W1,
                                            const float4* __restrict__ b1) {
    extern __shared__ __align__(16) __half dynh[];
    __half* As = dynh;                 // [128][ASH]
    __half* Wt = dynh + 128 * ASH;     // [128][ASH]
    int tid = threadIdx.x;
    int row0 = blockIdx.x * 128;
    // prologue: As[r][c] = fp16(relu(TSUM[r]*W1[c]+b1[c]))
    {
        int r = tid >> 2, q = tid & 3;
        int node = row0 + r; if (node >= NN) node = NN - 1;
        float s = TSUM[node];
        char* dst = reinterpret_cast<char*>(As) + r * (ASH * 2) + q * 64;
        #pragma unroll
        for (int j = 0; j < 8; j++) {
            float4 w = W1[q * 8 + j], b = b1[q * 8 + j];
            float z0 = fmaxf(fmaf(s, w.x, b.x), 0.f);
            float z1 = fmaxf(fmaf(s, w.y, b.y), 0.f);
            float z2 = fmaxf(fmaf(s, w.z, b.z), 0.f);
            float z3 = fmaxf(fmaf(s, w.w, b.w), 0.f);
            __half2 h0 = __floats2half2_rn(z0, z1);
            __half2 h1 = __floats2half2_rn(z2, z3);
            uint2 o;
            o.x = *reinterpret_cast<uint32_t*>(&h0);
            o.y = *reinterpret_cast<uint32_t*>(&h1);
            *reinterpret_cast<uint2*>(dst + j * 8) = o;
        }
    }
    load_wt_h<128>(Wt, W2, tid);
    __syncthreads();

    int wid = tid >> 5, lid = tid & 31;
    int g = lid >> 2, tig = lid & 3;
    int wm = wid >> 1, wn = wid & 1;
    float c[8][4] = {};
    hmma_loop<8>(c, As, Wt, wm, wn, g, tig);

    int r0 = row0 + wm * 16 + g;
    int r1 = r0 + 8;
    float s0 = (r0 < NN) ? DINV[r0] : 0.f;
    float s1 = (r1 < NN) ? DINV[r1] : 0.f;
    #pragma unroll
    for (int ni = 0; ni < 8; ni++) {
        int c2 = wn * 32 + ni * 4 + tig;
        if (r0 < NN)
            BUF_GH[(size_t)r0 * 64 + c2] = __floats2half2_rn(c[ni][0] * s0, c[ni][1] * s0);
        if (r1 < NN)
            BUF_GH[(size_t)r1 * 64 + c2] = __floats2half2_rn(c[ni][2] * s1, c[ni][3] * s1);
    }
}

// ---- layer 3 GEMM: BUF_GH = fp16(DINV * (BUF_ZH @ W3)) ----
__global__ void __launch_bounds__(512) k_gemm_mid(const float* __restrict__ W) {
    extern __shared__ __align__(16) __half dynh[];
    __half* As = dynh;
    __half* Wt = dynh + 128 * ASH;
    int tid = threadIdx.x;
    int row0 = blockIdx.x * 128;
    load_a_h(As, row0, tid);
    load_wt_h<128>(Wt, W, tid);
    __syncthreads();

    int wid = tid >> 5, lid = tid & 31;
    int g = lid >> 2, tig = lid & 3;
    int wm = wid >> 1, wn = wid & 1;
    float c[8][4] = {};
    hmma_loop<8>(c, As, Wt, wm, wn, g, tig);

    int r0 = row0 + wm * 16 + g;
    int r1 = r0 + 8;
    float s0 = (r0 < NN) ? DINV[r0] : 0.f;
    float s1 = (r1 < NN) ? DINV[r1] : 0.f;
    #pragma unroll
    for (int ni = 0; ni < 8; ni++) {
        int c2 = wn * 32 + ni * 4 + tig;
        if (r0 < NN)
            BUF_GH[(size_t)r0 * 64 + c2] = __floats2half2_rn(c[ni][0] * s0, c[ni][1] * s0);
        if (r1 < NN)
            BUF_GH[(size_t)r1 * 64 + c2] = __floats2half2_rn(c[ni][2] * s1, c[ni][3] * s1);
    }
}

// ---- head GEMM: out = (BUF_ZH @ Wo) + bo  (COUT=64, warp tile 16x32) ----
__global__ void __launch_bounds__(512) k_head(const float* __restrict__ W,
                                              const float* __restrict__ bias,
                                              float* __restrict__ outp) {
    extern __shared__ __align__(16) __half dynh[];
    __half* As = dynh;
    __half* Wt = dynh + 128 * ASH;     // [64][ASH]
    int tid = threadIdx.x;
    int row0 = blockIdx.x * 128;
    load_a_h(As, row0, tid);
    load_wt_h<64>(Wt, W, tid);
    __syncthreads();

    int wid = tid >> 5, lid = tid & 31;
    int g = lid >> 2, tig = lid & 3;
    int wm = wid >> 1, wn = wid & 1;
    float c[4][4] = {};
    hmma_loop<4>(c, As, Wt, wm, wn, g, tig);

    int r0 = row0 + wm * 16 + g;
    int r1 = r0 + 8;
    #pragma unroll
    for (int ni = 0; ni < 4; ni++) {
        int col = wn * 32 + ni * 8 + 2 * tig;
        float2 bb = *reinterpret_cast<const float2*>(bias + col);
        if (r0 < NN)
            *reinterpret_cast<float2*>(outp + (size_t)r0 * 64 + col) =
                make_float2(c[ni][0] + bb.x, c[ni][1] + bb.y);
        if (r1 < NN)
            *reinterpret_cast<float2*>(outp + (size_t)r1 * 64 + col) =
                make_float2(c[ni][2] + bb.x, c[ni][3] + bb.y);
    }
}

// ---------------- launch ----------------
extern "C" void kernel_launch(void* const* d_in, const int* in_sizes, int n_in,
                              void* d_out, int out_size) {
    const float* x  = (const float*)d_in[0];
    const int*   ei = (const int*)d_in[1];
    const int*   src = ei;
    const int*   dst = ei + EE;
    const float* W1 = (const float*)d_in[2];
    const float* b1 = (const float*)d_in[3];
    const float* W2 = (const float*)d_in[4];
    const float* b2 = (const float*)d_in[5];
    const float* W3 = (const float*)d_in[6];
    const float* b3 = (const float*)d_in[7];
    const float* Wo = (const float*)d_in[8];
    const float* bo = (const float*)d_in[9];
    float* out = (float*)d_out;

    cudaFuncSetAttribute(k_l2,       cudaFuncAttributeMaxDynamicSharedMemorySize, SMEM_G128);
    cudaFuncSetAttribute(k_gemm_mid, cudaFuncAttributeMaxDynamicSharedMemorySize, SMEM_G128);
    cudaFuncSetAttribute(k_head,     cudaFuncAttributeMaxDynamicSharedMemorySize, SMEM_G64);

    const int NG = (NN + 127) / 128;   // 782

    // CSR build
    k_zero   <<<(NN + 255) / 256, 256>>>();
    k_hist   <<<(EE + 255) / 256, 256>>>(dst);
    k_scan12 <<<(NN + 511) / 512, 512>>>(x);
    k_scan3  <<<(NN + 255) / 256, 256>>>();
    k_scatter<<<(EE + 255) / 256, 256>>>(src, dst);

    // layer 1 scalar aggregate + fused expand/GEMM(W2) -> messages
    k_scalar_agg<<<(NN + 255) / 256, 256>>>();
    k_l2<<<NG, 512, SMEM_G128>>>(W2, (const float4*)W1, (const float4*)b1);

    // layer 2 agg -> fp16 activations; layer 3 GEMM -> messages
    k_agg<true><<<(NN + 7) / 8, 256>>>((const float4*)b2);
    k_gemm_mid<<<NG, 512, SMEM_G128>>>(W3);

    // layer 3 agg -> fp16 activations; head GEMM -> out
    k_agg<false><<<(NN + 7) / 8, 256>>>((const float4*)b3);
    k_head<<<NG, 512, SMEM_G64>>>(Wo, bo, out);
}

// round 11
// speedup vs baseline: 1.8735x; 1.1941x over previous
#include <cuda_runtime.h>
#include <cuda_fp16.h>
#include <cstdint>

#define NN 100000
#define EE 1600000
#define HH 128

// ---------------- scratch (static device globals; no runtime alloc) ----------------
__device__ int     DEG[NN];
__device__ int     CURSOR[NN];
__device__ int     ROWPTR[NN + 1];
__device__ int     COLIDX[EE];
__device__ float   DINV[NN];
__device__ float   XD[NN];
__device__ float   TSUM[NN];
__device__ __half2 BUF_GH[(size_t)NN * (HH / 2)];   // fp16 messages
__device__ __half2 BUF_ZH[(size_t)NN * (HH / 2)];   // fp16 activations
__device__ float   WEFF[128 * 64];                  // W3 @ Wo
__device__ float   CEFF[64];                        // b3 @ Wo + bo
__device__ int     BLKSUM[256];
__device__ int     BLKOFF[256];
__device__ int     SCAN_CTR;

// ---------------- helpers ----------------
__device__ __forceinline__ void mma_f16(float c[4], uint32_t a0, uint32_t a1,
                                        uint32_t a2, uint32_t a3,
                                        uint32_t b0, uint32_t b1) {
    asm volatile(
        "mma.sync.aligned.m16n8k16.row.col.f32.f16.f16.f32 "
        "{%0,%1,%2,%3}, {%4,%5,%6,%7}, {%8,%9}, {%0,%1,%2,%3};"
        : "+f"(c[0]), "+f"(c[1]), "+f"(c[2]), "+f"(c[3])
        : "r"(a0), "r"(a1), "r"(a2), "r"(a3), "r"(b0), "r"(b1));
}

// ---------------- CSR build ----------------
__global__ void k_zero() {
    int i = blockIdx.x * blockDim.x + threadIdx.x;
    if (i < NN) { DEG[i] = 0; CURSOR[i] = 0; }
    if (i == 0) SCAN_CTR = 0;
}
__global__ void k_hist(const int* __restrict__ dst) {
    int e = blockIdx.x * blockDim.x + threadIdx.x;
    if (e < EE) atomicAdd(&DEG[dst[e]], 1);
}
__global__ void k_scan12(const float* __restrict__ x) {
    __shared__ int s[512];
    __shared__ int is_last;
    int i = blockIdx.x * 512 + threadIdx.x;
    int v = (i < NN) ? DEG[i] : 0;
    s[threadIdx.x] = v;
    __syncthreads();
    for (int off = 1; off < 512; off <<= 1) {
        int t = 0;
        if (threadIdx.x >= off) t = s[threadIdx.x - off];
        __syncthreads();
        if (threadIdx.x >= off) s[threadIdx.x] += t;
        __syncthreads();
    }
    if (i < NN) {
        ROWPTR[i] = s[threadIdx.x] - v;
        float di = rsqrtf((float)(v + 1));
        DINV[i] = di;
        XD[i] = x[i] * di;
    }
    if (threadIdx.x == 511) BLKSUM[blockIdx.x] = s[511];
    __threadfence();
    if (threadIdx.x == 0)
        is_last = (atomicAdd(&SCAN_CTR, 1) == gridDim.x - 1);
    __syncthreads();
    if (is_last && threadIdx.x < 256) {
        const int NB = (NN + 511) / 512;
        int bv = (threadIdx.x < NB) ? BLKSUM[threadIdx.x] : 0;
        s[threadIdx.x] = bv;
        __syncthreads();
        for (int off = 1; off < 256; off <<= 1) {
            int t = 0;
            if (threadIdx.x >= off) t = s[threadIdx.x - off];
            __syncthreads();
            if (threadIdx.x >= off) s[threadIdx.x] += t;
            __syncthreads();
        }
        BLKOFF[threadIdx.x] = s[threadIdx.x] - bv;
    }
}
__global__ void k_scan3() {
    int i = blockIdx.x * blockDim.x + threadIdx.x;
    if (i < NN) ROWPTR[i] += BLKOFF[i >> 9];
    if (i == 0) ROWPTR[NN] = EE;
}
__global__ void k_scatter(const int* __restrict__ src, const int* __restrict__ dst) {
    int e = blockIdx.x * blockDim.x + threadIdx.x;
    if (e >= EE) return;
    int d = dst[e];
    int p = ROWPTR[d] + atomicAdd(&CURSOR[d], 1);
    COLIDX[p] = src[e];
}

// ---------------- precompute Weff = W3 @ Wo, CEFF = b3 @ Wo + bo ----------------
__global__ void __launch_bounds__(512) k_weff(const float* __restrict__ W3,
                                              const float* __restrict__ Wo,
                                              const float* __restrict__ b3,
                                              const float* __restrict__ bo) {
    int idx = blockIdx.x * blockDim.x + threadIdx.x;   // 8192 = 128*64
    int k = idx >> 6, n = idx & 63;
    float s = 0.f;
    #pragma unroll 8
    for (int j = 0; j < 128; j++) s = fmaf(W3[k * 128 + j], Wo[j * 64 + n], s);
    WEFF[k * 64 + n] = s;
    if (idx < 64) {
        float c = 0.f;
        #pragma unroll 8
        for (int j = 0; j < 128; j++) c = fmaf(b3[j], Wo[j * 64 + idx], c);
        CEFF[idx] = c + bo[idx];
    }
}

// ---------------- layer-1 scalar aggregation ----------------
__global__ void k_scalar_agg() {
    int i = blockIdx.x * blockDim.x + threadIdx.x;
    if (i >= NN) return;
    float t = XD[i];
    int e = ROWPTR[i], end = ROWPTR[i + 1];
    for (; e + 4 <= end; e += 4) {
        float a0 = XD[COLIDX[e]],     a1 = XD[COLIDX[e + 1]];
        float a2 = XD[COLIDX[e + 2]], a3 = XD[COLIDX[e + 3]];
        t += (a0 + a1) + (a2 + a3);
    }
    for (; e < end; ++e) t += XD[COLIDX[e]];
    TSUM[i] = t * DINV[i];
}

// ---------------- layer-2 aggregation (128-wide fp16 messages -> fp16 act, relu) -----
__device__ __forceinline__ void acc_gh(float4& acc, uint2 u) {
    float2 f0 = __half22float2(*reinterpret_cast<__half2*>(&u.x));
    float2 f1 = __half22float2(*reinterpret_cast<__half2*>(&u.y));
    acc.x += f0.x; acc.y += f0.y; acc.z += f1.x; acc.w += f1.y;
}

__global__ void k_agg_relu(const float4* __restrict__ bias) {
    int node = (blockIdx.x * blockDim.x + threadIdx.x) >> 5;
    if (node >= NN) return;
    int lane = threadIdx.x & 31;
    const uint2* g = reinterpret_cast<const uint2*>(BUF_GH);
    float4 acc = make_float4(0.f, 0.f, 0.f, 0.f);
    acc_gh(acc, g[node * 32 + lane]);                 // self-loop term
    int e = ROWPTR[node], end = ROWPTR[node + 1];
    for (; e + 4 <= end; e += 4) {
        int s0 = COLIDX[e], s1 = COLIDX[e + 1], s2 = COLIDX[e + 2], s3 = COLIDX[e + 3];
        uint2 u0 = g[s0 * 32 + lane], u1 = g[s1 * 32 + lane];
        uint2 u2 = g[s2 * 32 + lane], u3 = g[s3 * 32 + lane];
        acc_gh(acc, u0); acc_gh(acc, u1); acc_gh(acc, u2); acc_gh(acc, u3);
    }
    for (; e < end; ++e) acc_gh(acc, g[COLIDX[e] * 32 + lane]);
    float di = DINV[node];
    float4 b = bias[lane];
    float4 r = make_float4(fmaxf(fmaf(acc.x, di, b.x), 0.f),
                           fmaxf(fmaf(acc.y, di, b.y), 0.f),
                           fmaxf(fmaf(acc.z, di, b.z), 0.f),
                           fmaxf(fmaf(acc.w, di, b.w), 0.f));
    __half2 h0 = __floats2half2_rn(r.x, r.y);
    __half2 h1 = __floats2half2_rn(r.z, r.w);
    uint2 o;
    o.x = *reinterpret_cast<uint32_t*>(&h0);
    o.y = *reinterpret_cast<uint32_t*>(&h1);
    reinterpret_cast<uint2*>(BUF_ZH)[node * 32 + lane] = o;
}

// ---------------- final aggregation (64-wide fp16 messages -> out fp32 + CEFF) -------
__global__ void k_agg_out(float* __restrict__ outp) {
    int node = (blockIdx.x * blockDim.x + threadIdx.x) >> 5;
    if (node >= NN) return;
    int lane = threadIdx.x & 31;
    const uint32_t* g = reinterpret_cast<const uint32_t*>(BUF_GH);  // 32 uints/row
    float2 acc = make_float2(0.f, 0.f);
    {
        uint32_t u = g[node * 32 + lane];
        float2 f = __half22float2(*reinterpret_cast<__half2*>(&u));
        acc.x += f.x; acc.y += f.y;
    }
    int e = ROWPTR[node], end = ROWPTR[node + 1];
    for (; e + 4 <= end; e += 4) {
        int s0 = COLIDX[e], s1 = COLIDX[e + 1], s2 = COLIDX[e + 2], s3 = COLIDX[e + 3];
        uint32_t u0 = g[s0 * 32 + lane], u1 = g[s1 * 32 + lane];
        uint32_t u2 = g[s2 * 32 + lane], u3 = g[s3 * 32 + lane];
        float2 f0 = __half22float2(*reinterpret_cast<__half2*>(&u0));
        float2 f1 = __half22float2(*reinterpret_cast<__half2*>(&u1));
        float2 f2 = __half22float2(*reinterpret_cast<__half2*>(&u2));
        float2 f3 = __half22float2(*reinterpret_cast<__half2*>(&u3));
        acc.x += (f0.x + f1.x) + (f2.x + f3.x);
        acc.y += (f0.y + f1.y) + (f2.y + f3.y);
    }
    for (; e < end; ++e) {
        uint32_t u = g[COLIDX[e] * 32 + lane];
        float2 f = __half22float2(*reinterpret_cast<__half2*>(&u));
        acc.x += f.x; acc.y += f.y;
    }
    float di = DINV[node];
    float2 cb = *reinterpret_cast<const float2*>(CEFF + 2 * lane);
    *reinterpret_cast<float2*>(outp + (size_t)node * 64 + 2 * lane) =
        make_float2(fmaf(acc.x, di, cb.x), fmaf(acc.y, di, cb.y));
}

// ================= fp16 HMMA GEMMs (BM=128, 512 threads, 16 warps) ==================
#define ASH 136
#define SMEM_G128 ((128 * ASH + 128 * ASH) * 2)
#define SMEM_G64  ((128 * ASH + 64 * ASH) * 2)

__device__ __forceinline__ void load_a_h(__half* As, int row0, int tid) {
    const uint4* Z4 = reinterpret_cast<const uint4*>(BUF_ZH);
    #pragma unroll
    for (int i = 0; i < 4; i++) {
        int idx = i * 512 + tid;
        int rr = idx >> 4, q = idx & 15;
        int grow = row0 + rr; if (grow >= NN) grow = NN - 1;
        uint4 u = Z4[(size_t)grow * 16 + q];
        *reinterpret_cast<uint4*>(reinterpret_cast<char*>(As) + rr * (ASH * 2) + q * 16) = u;
    }
}

template <int NC, bool DEV>   // DEV: W is a __device__ global (no __restrict__ benefit)
__device__ __forceinline__ void load_wt_h(__half* Wt, const float* W, int tid) {
    const float4* W4 = reinterpret_cast<const float4*>(W);
    constexpr int ITERS = 128 * (NC / 4) / 512;
    #pragma unroll
    for (int i = 0; i < ITERS; i++) {
        int idx = i * 512 + tid;
        int kr = idx / (NC / 4), q = idx % (NC / 4);
        float4 v = W4[kr * (NC / 4) + q];
        Wt[(q * 4 + 0) * ASH + kr] = __float2half_rn(v.x);
        Wt[(q * 4 + 1) * ASH + kr] = __float2half_rn(v.y);
        Wt[(q * 4 + 2) * ASH + kr] = __float2half_rn(v.z);
        Wt[(q * 4 + 3) * ASH + kr] = __float2half_rn(v.w);
    }
}

template <int NI>
__device__ __forceinline__ void hmma_loop(float c[NI][4], const __half* As,
                                          const __half* Wt, int wm, int wn,
                                          int g, int tig) {
    const char* Ab = reinterpret_cast<const char*>(As);
    const char* Wb = reinterpret_cast<const char*>(Wt);
    #pragma unroll
    for (int ks = 0; ks < 8; ks++) {
        int k0 = ks * 16;
        int rb = wm * 16 + g;
        uint32_t a0 = *reinterpret_cast<const uint32_t*>(Ab + (rb * ASH + k0 + 2 * tig) * 2);
        uint32_t a1 = *reinterpret_cast<const uint32_t*>(Ab + ((rb + 8) * ASH + k0 + 2 * tig) * 2);
        uint32_t a2 = *reinterpret_cast<const uint32_t*>(Ab + (rb * ASH + k0 + 8 + 2 * tig) * 2);
        uint32_t a3 = *reinterpret_cast<const uint32_t*>(Ab + ((rb + 8) * ASH + k0 + 8 + 2 * tig) * 2);
        #pragma unroll
        for (int ni = 0; ni < NI; ni++) {
            int n = wn * (8 * NI) + ni * 8 + g;
            uint32_t b0 = *reinterpret_cast<const uint32_t*>(Wb + (n * ASH + k0 + 2 * tig) * 2);
            uint32_t b1 = *reinterpret_cast<const uint32_t*>(Wb + (n * ASH + k0 + 8 + 2 * tig) * 2);
            mma_f16(c[ni], a0, a1, a2, a3, b0, b1);
        }
    }
}

// ---- layer 2: expand prologue (rank-1) fused into GEMM(W2) -> 128-wide messages ----
__global__ void __launch_bounds__(512) k_l2(const float* __restrict__ W2,
                                            const float4* __restrict__ W1,
                                            const float4* __restrict__ b1) {
    extern __shared__ __align__(16) __half dynh[];
    __half* As = dynh;
    __half* Wt = dynh + 128 * ASH;
    int tid = threadIdx.x;
    int row0 = blockIdx.x * 128;
    {
        int r = tid >> 2, q = tid & 3;
        int node = row0 + r; if (node >= NN) node = NN - 1;
        float s = TSUM[node];
        char* dst = reinterpret_cast<char*>(As) + r * (ASH * 2) + q * 64;
        #pragma unroll
        for (int j = 0; j < 8; j++) {
            float4 w = W1[q * 8 + j], b = b1[q * 8 + j];
            float z0 = fmaxf(fmaf(s, w.x, b.x), 0.f);
            float z1 = fmaxf(fmaf(s, w.y, b.y), 0.f);
            float z2 = fmaxf(fmaf(s, w.z, b.z), 0.f);
            float z3 = fmaxf(fmaf(s, w.w, b.w), 0.f);
            __half2 h0 = __floats2half2_rn(z0, z1);
            __half2 h1 = __floats2half2_rn(z2, z3);
            uint2 o;
            o.x = *reinterpret_cast<uint32_t*>(&h0);
            o.y = *reinterpret_cast<uint32_t*>(&h1);
            *reinterpret_cast<uint2*>(dst + j * 8) = o;
        }
    }
    load_wt_h<128, false>(Wt, W2, tid);
    __syncthreads();

    int wid = tid >> 5, lid = tid & 31;
    int g = lid >> 2, tig = lid & 3;
    int wm = wid >> 1, wn = wid & 1;
    float c[8][4] = {};
    hmma_loop<8>(c, As, Wt, wm, wn, g, tig);

    int r0 = row0 + wm * 16 + g;
    int r1 = r0 + 8;
    float s0 = (r0 < NN) ? DINV[r0] : 0.f;
    float s1 = (r1 < NN) ? DINV[r1] : 0.f;
    #pragma unroll
    for (int ni = 0; ni < 8; ni++) {
        int c2 = wn * 32 + ni * 4 + tig;
        if (r0 < NN)
            BUF_GH[(size_t)r0 * 64 + c2] = __floats2half2_rn(c[ni][0] * s0, c[ni][1] * s0);
        if (r1 < NN)
            BUF_GH[(size_t)r1 * 64 + c2] = __floats2half2_rn(c[ni][2] * s1, c[ni][3] * s1);
    }
}

// ---- effective GEMM: 64-wide messages m = fp16(DINV * (BUF_ZH @ WEFF)), stride 32 ----
__global__ void __launch_bounds__(512) k_gemm_eff() {
    extern __shared__ __align__(16) __half dynh[];
    __half* As = dynh;
    __half* Wt = dynh + 128 * ASH;     // [64][ASH]
    int tid = threadIdx.x;
    int row0 = blockIdx.x * 128;
    load_a_h(As, row0, tid);
    load_wt_h<64, true>(Wt, WEFF, tid);
    __syncthreads();

    int wid = tid >> 5, lid = tid & 31;
    int g = lid >> 2, tig = lid & 3;
    int wm = wid >> 1, wn = wid & 1;
    float c[4][4] = {};
    hmma_loop<4>(c, As, Wt, wm, wn, g, tig);

    int r0 = row0 + wm * 16 + g;
    int r1 = r0 + 8;
    float s0 = (r0 < NN) ? DINV[r0] : 0.f;
    float s1 = (r1 < NN) ? DINV[r1] : 0.f;
    #pragma unroll
    for (int ni = 0; ni < 4; ni++) {
        int c2 = wn * 16 + ni * 4 + tig;   // half2 col 0..31, row stride 32
        if (r0 < NN)
            BUF_GH[(size_t)r0 * 32 + c2] = __floats2half2_rn(c[ni][0] * s0, c[ni][1] * s0);
        if (r1 < NN)
            BUF_GH[(size_t)r1 * 32 + c2] = __floats2half2_rn(c[ni][2] * s1, c[ni][3] * s1);
    }
}

// ---------------- launch ----------------
extern "C" void kernel_launch(void* const* d_in, const int* in_sizes, int n_in,
                              void* d_out, int out_size) {
    const float* x  = (const float*)d_in[0];
    const int*   ei = (const int*)d_in[1];
    const int*   src = ei;
    const int*   dst = ei + EE;
    const float* W1 = (const float*)d_in[2];
    const float* b1 = (const float*)d_in[3];
    const float* W2 = (const float*)d_in[4];
    const float* b2 = (const float*)d_in[5];
    const float* W3 = (const float*)d_in[6];
    const float* b3 = (const float*)d_in[7];
    const float* Wo = (const float*)d_in[8];
    const float* bo = (const float*)d_in[9];
    float* out = (float*)d_out;

    cudaFuncSetAttribute(k_l2,       cudaFuncAttributeMaxDynamicSharedMemorySize, SMEM_G128);
    cudaFuncSetAttribute(k_gemm_eff, cudaFuncAttributeMaxDynamicSharedMemorySize, SMEM_G64);

    const int NG = (NN + 127) / 128;   // 782

    // CSR build + Weff precompute
    k_zero   <<<(NN + 255) / 256, 256>>>();
    k_hist   <<<(EE + 255) / 256, 256>>>(dst);
    k_scan12 <<<(NN + 511) / 512, 512>>>(x);
    k_scan3  <<<(NN + 255) / 256, 256>>>();
    k_scatter<<<(EE + 255) / 256, 256>>>(src, dst);
    k_weff   <<<16, 512>>>(W3, Wo, b3, bo);

    // layer 1 scalar aggregate + fused expand/GEMM(W2) -> 128-wide messages
    k_scalar_agg<<<(NN + 255) / 256, 256>>>();
    k_l2<<<NG, 512, SMEM_G128>>>(W2, (const float4*)W1, (const float4*)b1);

    // layer 2 agg (relu) -> fp16 activations
    k_agg_relu<<<(NN + 7) / 8, 256>>>((const float4*)b2);

    // fused layer3+head GEMM -> 64-wide messages; final agg -> out
    k_gemm_eff<<<NG, 512, SMEM_G64>>>();
    k_agg_out<<<(NN + 7) / 8, 256>>>(out);
}